// round 9
// baseline (speedup 1.0000x reference)
#include <cuda_runtime.h>
#include <cuda_fp16.h>
#include <cstdint>

#define N_NODES 100000
#define N_REL   4
#define N_EDGES 600000
#define D       128
#define KTOT    (N_REL * D)   // 512
#define RN      (N_REL * N_NODES)   // 400000

// Scratch (device globals — no allocation allowed in kernel_launch)
__device__ __half g_Y [(size_t)N_NODES * KTOT];      // [N, 4, 128] fp16: rs_out*(X@W_r)
__device__ __half g_Xh[(size_t)N_NODES * D];         // X in fp16
__device__ __half g_Wt[(size_t)N_REL * D * D];       // W[r] transposed: [r][n][k] fp16
__device__ int    g_cnt_out[RN];                     // out-degree  [r][n]
__device__ int    g_cnt_in [RN];                     // in-degree   [r][n]
__device__ int    g_rowptr [RN + 1];                 // CSR row ptr (global offsets)
__device__ int    g_cursor [RN];                     // fill cursors (copy of rowptr)
__device__ int    g_csr    [N_REL * N_EDGES];        // src indices bucketed by (r, dst)

// ---------------------------------------------------------------------------
// Degree histogram: one thread per (relation, edge), two int atomics.
__global__ void degree_kernel(const int* __restrict__ edges) {
    int i = blockIdx.x * blockDim.x + threadIdx.x;
    if (i >= N_REL * N_EDGES) return;
    int r = i / N_EDGES;
    int e = i - r * N_EDGES;
    int s = edges[(r * 2 + 0) * N_EDGES + e];
    int t = edges[(r * 2 + 1) * N_EDGES + e];
    atomicAdd(&g_cnt_out[r * N_NODES + s], 1);
    atomicAdd(&g_cnt_in [r * N_NODES + t], 1);
}

// ---------------------------------------------------------------------------
// Single-block exclusive scan of g_cnt_in[0..RN) -> g_rowptr. 1024 threads,
// each owns a contiguous chunk: serial local sum, block Hillis-Steele scan of
// the 1024 partials, then serial chunk re-walk writing running offsets.
__global__ __launch_bounds__(1024) void scan_kernel() {
    __shared__ int ssum[1024];
    const int T = 1024;
    const int chunk = (RN + T - 1) / T;   // 391
    int tid = threadIdx.x;
    int b = tid * chunk;
    int e = min(b + chunk, RN);

    int sum = 0;
#pragma unroll 4
    for (int i = b; i < e; i++) sum += __ldg(&g_cnt_in[i]);
    ssum[tid] = sum;
    __syncthreads();

    for (int off = 1; off < T; off <<= 1) {
        int v = (tid >= off) ? ssum[tid - off] : 0;
        __syncthreads();
        ssum[tid] += v;
        __syncthreads();
    }
    int run = (tid == 0) ? 0 : ssum[tid - 1];

    for (int i = b; i < e; i++) {
        g_rowptr[i] = run;
        run += __ldg(&g_cnt_in[i]);
    }
    if (tid == T - 1) g_rowptr[RN] = run;
}

// ---------------------------------------------------------------------------
// CSR fill: per edge, grab a slot in its (r, dst) bucket, store src.
__global__ void csr_fill_kernel(const int* __restrict__ edges) {
    int i = blockIdx.x * blockDim.x + threadIdx.x;
    if (i >= N_REL * N_EDGES) return;
    int r = i / N_EDGES;
    int e = i - r * N_EDGES;
    int s = edges[(r * 2 + 0) * N_EDGES + e];
    int t = edges[(r * 2 + 1) * N_EDGES + e];
    int slot = atomicAdd(&g_cursor[r * N_NODES + t], 1);
    g_csr[slot] = s;
}

// ---------------------------------------------------------------------------
// One-time conversions.
__global__ void convert_x_kernel(const float* __restrict__ X) {
    int i = blockIdx.x * blockDim.x + threadIdx.x;
    size_t total8 = (size_t)N_NODES * D / 8;
    if ((size_t)i >= total8) return;
    const float4* src = (const float4*)X + (size_t)i * 2;
    float4 a = __ldg(src);
    float4 b = __ldg(src + 1);
    __half2 h0 = __floats2half2_rn(a.x, a.y);
    __half2 h1 = __floats2half2_rn(a.z, a.w);
    __half2 h2 = __floats2half2_rn(b.x, b.y);
    __half2 h3 = __floats2half2_rn(b.z, b.w);
    uint4 u;
    u.x = *(uint32_t*)&h0; u.y = *(uint32_t*)&h1;
    u.z = *(uint32_t*)&h2; u.w = *(uint32_t*)&h3;
    *((uint4*)g_Xh + i) = u;
}

// W[r][k][n] f32 -> g_Wt[r][n][k] f16 (transposed per relation).
__global__ void convert_w_kernel(const float* __restrict__ W) {
    int i = blockIdx.x * blockDim.x + threadIdx.x;
    if (i >= N_REL * D * D) return;
    int r = i >> 14;
    int rem = i & 16383;
    int k = rem >> 7;
    int n = rem & 127;
    g_Wt[((size_t)r * D + n) * D + k] = __float2half_rn(__ldg(&W[i]));
}

// ---------------------------------------------------------------------------
// FP16 tensor-core GEMM producing Y' = rs_out_r * (Xh @ W_r), stored fp16.
// C-block: 128x128; grid.y = relation. K = 128, BK = 32. 8 warps (2M x 4N),
// warp tile 64x32, m16n8k16 f16 mma, f32 acc. Smem stride 20 words.
#define GBM 128
#define GBN 128
#define GBK 32
#define SSTRIDE 20

__device__ __forceinline__ void mma_f16(float* d, const uint32_t* a,
                                        const uint32_t* b) {
    asm volatile(
        "mma.sync.aligned.m16n8k16.row.col.f32.f16.f16.f32 "
        "{%0,%1,%2,%3}, {%4,%5,%6,%7}, {%8,%9}, {%0,%1,%2,%3};"
        : "+f"(d[0]), "+f"(d[1]), "+f"(d[2]), "+f"(d[3])
        : "r"(a[0]), "r"(a[1]), "r"(a[2]), "r"(a[3]), "r"(b[0]), "r"(b[1]));
}

__global__ __launch_bounds__(256, 2)
void gemm_f16_kernel(const __half* __restrict__ Xh, const __half* __restrict__ Wt,
                     __half* __restrict__ Y) {
    __shared__ __align__(16) uint32_t As[GBM][SSTRIDE];
    __shared__ __align__(16) uint32_t Bs[GBN][SSTRIDE];

    int tid  = threadIdx.x;
    int wid  = tid >> 5;
    int lane = tid & 31;
    int lg   = lane >> 2;
    int lt   = lane & 3;
    int warp_m = wid & 1;
    int warp_n = wid >> 1;
    int row0 = blockIdx.x * GBM;
    int rel  = blockIdx.y;
    const __half* Bt = Wt + (size_t)rel * (D * D);

    float acc[4][4][4];
#pragma unroll
    for (int mi = 0; mi < 4; mi++)
#pragma unroll
        for (int ni = 0; ni < 4; ni++)
#pragma unroll
            for (int j = 0; j < 4; j++) acc[mi][ni][j] = 0.0f;

    for (int k0 = 0; k0 < D; k0 += GBK) {
#pragma unroll
        for (int i = 0; i < 2; i++) {
            int idx = tid + i * 256;
            int row = idx >> 2;
            int ch  = idx & 3;
            int grow = min(row0 + row, N_NODES - 1);
            uint4 u = __ldg((const uint4*)(Xh + (size_t)grow * D + k0 + ch * 8));
            *(uint4*)&As[row][ch * 4] = u;
        }
#pragma unroll
        for (int i = 0; i < 2; i++) {
            int idx = tid + i * 256;
            int col = idx >> 2;
            int ch  = idx & 3;
            uint4 u = __ldg((const uint4*)(Bt + (size_t)col * D + k0 + ch * 8));
            *(uint4*)&Bs[col][ch * 4] = u;
        }
        __syncthreads();

#pragma unroll
        for (int ks = 0; ks < 2; ks++) {
            int kc = ks * 8;
            uint32_t af[4][4];
            uint32_t bf[4][2];
#pragma unroll
            for (int mi = 0; mi < 4; mi++) {
                int base = warp_m * 64 + mi * 16;
                af[mi][0] = As[base + lg    ][kc + lt    ];
                af[mi][1] = As[base + lg + 8][kc + lt    ];
                af[mi][2] = As[base + lg    ][kc + lt + 4];
                af[mi][3] = As[base + lg + 8][kc + lt + 4];
            }
#pragma unroll
            for (int ni = 0; ni < 4; ni++) {
                int col = warp_n * 32 + ni * 8 + lg;
                bf[ni][0] = Bs[col][kc + lt    ];
                bf[ni][1] = Bs[col][kc + lt + 4];
            }
#pragma unroll
            for (int mi = 0; mi < 4; mi++)
#pragma unroll
                for (int ni = 0; ni < 4; ni++)
                    mma_f16(acc[mi][ni], af[mi], bf[ni]);
        }
        __syncthreads();
    }

    // Epilogue: scale by rsqrt(max(deg_out,1)) computed inline from counts.
    const int* cnt_out = g_cnt_out + (size_t)rel * N_NODES;
#pragma unroll
    for (int mi = 0; mi < 4; mi++) {
        int r = row0 + warp_m * 64 + mi * 16 + lg;
        float s0 = 0.0f, s1 = 0.0f;
        if (r < N_NODES)
            s0 = rsqrtf(fmaxf((float)__ldg(&cnt_out[r]), 1.0f));
        if (r + 8 < N_NODES)
            s1 = rsqrtf(fmaxf((float)__ldg(&cnt_out[r + 8]), 1.0f));
#pragma unroll
        for (int ni = 0; ni < 4; ni++) {
            int c = warp_n * 32 + ni * 8 + 2 * lt;
            if (r < N_NODES) {
                __half2 h = __floats2half2_rn(acc[mi][ni][0] * s0,
                                              acc[mi][ni][1] * s0);
                *(__half2*)(Y + (size_t)r * KTOT + rel * D + c) = h;
            }
            if (r + 8 < N_NODES) {
                __half2 h = __floats2half2_rn(acc[mi][ni][2] * s1,
                                              acc[mi][ni][3] * s1);
                *(__half2*)(Y + (size_t)(r + 8) * KTOT + rel * D + c) = h;
            }
        }
    }
}

// ---------------------------------------------------------------------------
// Gather: one warp per dst node. Lane l owns cols 4l..4l+3. For each relation,
// sum Y[src] rows over the CSR in-edge list (2-edge unroll for MLP), scale by
// rsqrt(deg_in) factored OUT of the sum, accumulate across relations, write
// the out row exactly once. No atomics anywhere.
__global__ __launch_bounds__(256)
void gather_kernel(const __half* __restrict__ Y, float* __restrict__ out) {
    int warp = (blockIdx.x * blockDim.x + threadIdx.x) >> 5;
    if (warp >= N_NODES) return;
    int lane = threadIdx.x & 31;
    int t = warp;

    float a0 = 0.f, a1 = 0.f, a2 = 0.f, a3 = 0.f;

#pragma unroll
    for (int r = 0; r < N_REL; r++) {
        int start = __ldg(&g_rowptr[r * N_NODES + t]);
        int end   = __ldg(&g_rowptr[r * N_NODES + t + 1]);
        float ci = rsqrtf(fmaxf((float)(end - start), 1.0f));
        const __half* Yr = Y + (size_t)r * D;

        float r0 = 0.f, r1 = 0.f, r2 = 0.f, r3 = 0.f;
        int j = start;
        for (; j + 2 <= end; j += 2) {
            int s0 = __ldg(&g_csr[j]);
            int s1 = __ldg(&g_csr[j + 1]);
            uint2 v0 = __ldg((const uint2*)(Yr + (size_t)s0 * KTOT) + lane);
            uint2 v1 = __ldg((const uint2*)(Yr + (size_t)s1 * KTOT) + lane);
            float2 p0 = __half22float2(*(__half2*)&v0.x);
            float2 p1 = __half22float2(*(__half2*)&v0.y);
            float2 q0 = __half22float2(*(__half2*)&v1.x);
            float2 q1 = __half22float2(*(__half2*)&v1.y);
            r0 += p0.x + q0.x;
            r1 += p0.y + q0.y;
            r2 += p1.x + q1.x;
            r3 += p1.y + q1.y;
        }
        if (j < end) {
            int s0 = __ldg(&g_csr[j]);
            uint2 v0 = __ldg((const uint2*)(Yr + (size_t)s0 * KTOT) + lane);
            float2 p0 = __half22float2(*(__half2*)&v0.x);
            float2 p1 = __half22float2(*(__half2*)&v0.y);
            r0 += p0.x; r1 += p0.y; r2 += p1.x; r3 += p1.y;
        }
        a0 = fmaf(ci, r0, a0);
        a1 = fmaf(ci, r1, a1);
        a2 = fmaf(ci, r2, a2);
        a3 = fmaf(ci, r3, a3);
    }

    float4 o = make_float4(a0, a1, a2, a3);
    *(float4*)(out + (size_t)t * D + lane * 4) = o;
}

// ---------------------------------------------------------------------------
extern "C" void kernel_launch(void* const* d_in, const int* in_sizes, int n_in,
                              void* d_out, int out_size) {
    const int*   edges = (const int*)d_in[0];    // [4, 2, 600000] int32
    const float* X     = (const float*)d_in[1];  // [100000, 128] f32
    const float* W     = (const float*)d_in[2];  // [4, 128, 128] f32
    float*       out   = (float*)d_out;          // [100000, 128] f32

    void *yp, *xhp, *wtp, *cop, *cip, *rpp, *cup;
    cudaGetSymbolAddress(&yp,  g_Y);
    cudaGetSymbolAddress(&xhp, g_Xh);
    cudaGetSymbolAddress(&wtp, g_Wt);
    cudaGetSymbolAddress(&cop, g_cnt_out);
    cudaGetSymbolAddress(&cip, g_cnt_in);
    cudaGetSymbolAddress(&rpp, g_rowptr);
    cudaGetSymbolAddress(&cup, g_cursor);

    cudaMemsetAsync(cop, 0, sizeof(int) * RN, 0);
    cudaMemsetAsync(cip, 0, sizeof(int) * RN, 0);

    {
        int total = N_REL * N_EDGES;
        degree_kernel<<<(total + 255) / 256, 256>>>(edges);
    }
    {
        size_t total8 = (size_t)N_NODES * D / 8;
        convert_x_kernel<<<(int)((total8 + 255) / 256), 256>>>(X);
    }
    {
        int total = N_REL * D * D;
        convert_w_kernel<<<(total + 255) / 256, 256>>>(W);
    }
    scan_kernel<<<1, 1024>>>();
    cudaMemcpyAsync(cup, rpp, sizeof(int) * RN, cudaMemcpyDeviceToDevice, 0);
    {
        int total = N_REL * N_EDGES;
        csr_fill_kernel<<<(total + 255) / 256, 256>>>(edges);
    }
    {
        dim3 grid((N_NODES + GBM - 1) / GBM, N_REL);   // (782, 4)
        gemm_f16_kernel<<<grid, 256>>>((const __half*)xhp, (const __half*)wtp,
                                       (__half*)yp);
    }
    {
        // one warp per dst node
        long long threads = (long long)N_NODES * 32;
        int blocks = (int)((threads + 255) / 256);
        gather_kernel<<<blocks, 256>>>((const __half*)yp, out);
    }
}

// round 10
// speedup vs baseline: 2.2406x; 2.2406x over previous
#include <cuda_runtime.h>
#include <cuda_fp16.h>
#include <cstdint>

#define N_NODES 100000
#define N_REL   4
#define N_EDGES 600000
#define D       128
#define KTOT    (N_REL * D)   // 512
#define RN      (N_REL * N_NODES)   // 400000
#define SCAN_BLK 1024
#define SCAN_NBLK ((RN + SCAN_BLK - 1) / SCAN_BLK)   // 391

// Scratch (device globals — no allocation allowed in kernel_launch)
__device__ __half g_Y [(size_t)N_NODES * KTOT];      // [N, 4, 128] fp16: rs_out*(X@W_r)
__device__ __half g_Xh[(size_t)N_NODES * D];         // X in fp16
__device__ __half g_Wt[(size_t)N_REL * D * D];       // W[r] transposed: [r][n][k] fp16
__device__ int    g_cnt_out[RN];                     // out-degree  [r][n]
__device__ int    g_cnt_in [RN];                     // in-degree   [r][n]
__device__ int    g_rowptr [RN + 1];                 // CSR row ptr (global offsets)
__device__ int    g_cursor [RN];                     // fill cursors (copy of rowptr)
__device__ int    g_blocksum[SCAN_NBLK];             // per-block totals (phase 1)
__device__ int    g_blockoff[SCAN_NBLK];             // exclusive block offsets (phase 2)
__device__ int    g_csr    [N_REL * N_EDGES];        // src indices bucketed by (r, dst)

// ---------------------------------------------------------------------------
// Degree histogram: one thread per (relation, edge), two int atomics.
__global__ void degree_kernel(const int* __restrict__ edges) {
    int i = blockIdx.x * blockDim.x + threadIdx.x;
    if (i >= N_REL * N_EDGES) return;
    int r = i / N_EDGES;
    int e = i - r * N_EDGES;
    int s = edges[(r * 2 + 0) * N_EDGES + e];
    int t = edges[(r * 2 + 1) * N_EDGES + e];
    atomicAdd(&g_cnt_out[r * N_NODES + s], 1);
    atomicAdd(&g_cnt_in [r * N_NODES + t], 1);
}

// ---------------------------------------------------------------------------
// 3-phase parallel exclusive scan of g_cnt_in -> g_rowptr (+ g_cursor copy).
// Phase 1: per-block inclusive scan (Hillis-Steele, 1024 wide); write
// block-exclusive partials into g_rowptr and block totals to g_blocksum.
__global__ __launch_bounds__(SCAN_BLK) void scan_phase1_kernel() {
    __shared__ int s[SCAN_BLK];
    int tid = threadIdx.x;
    int i = blockIdx.x * SCAN_BLK + tid;
    int v = (i < RN) ? __ldg(&g_cnt_in[i]) : 0;
    s[tid] = v;
    __syncthreads();
#pragma unroll
    for (int off = 1; off < SCAN_BLK; off <<= 1) {
        int add = (tid >= off) ? s[tid - off] : 0;
        __syncthreads();
        s[tid] += add;
        __syncthreads();
    }
    if (i < RN) g_rowptr[i] = s[tid] - v;          // exclusive within block
    if (tid == SCAN_BLK - 1) g_blocksum[blockIdx.x] = s[tid];
}

// Phase 2: single small block scans the 391 block sums (exclusive).
__global__ __launch_bounds__(512) void scan_phase2_kernel() {
    __shared__ int s[512];
    int tid = threadIdx.x;
    int v = (tid < SCAN_NBLK) ? g_blocksum[tid] : 0;
    s[tid] = v;
    __syncthreads();
#pragma unroll
    for (int off = 1; off < 512; off <<= 1) {
        int add = (tid >= off) ? s[tid - off] : 0;
        __syncthreads();
        s[tid] += add;
        __syncthreads();
    }
    if (tid < SCAN_NBLK) g_blockoff[tid] = s[tid] - v;
    if (tid == 0) g_rowptr[RN] = N_REL * N_EDGES;  // grand total is constant
}

// Phase 3: add block offsets; write cursor copy in the same pass.
__global__ __launch_bounds__(SCAN_BLK) void scan_phase3_kernel() {
    int i = blockIdx.x * SCAN_BLK + threadIdx.x;
    if (i >= RN) return;
    int v = g_rowptr[i] + __ldg(&g_blockoff[blockIdx.x]);
    g_rowptr[i] = v;
    g_cursor[i] = v;
}

// ---------------------------------------------------------------------------
// CSR fill: per edge, grab a slot in its (r, dst) bucket, store src.
__global__ void csr_fill_kernel(const int* __restrict__ edges) {
    int i = blockIdx.x * blockDim.x + threadIdx.x;
    if (i >= N_REL * N_EDGES) return;
    int r = i / N_EDGES;
    int e = i - r * N_EDGES;
    int s = edges[(r * 2 + 0) * N_EDGES + e];
    int t = edges[(r * 2 + 1) * N_EDGES + e];
    int slot = atomicAdd(&g_cursor[r * N_NODES + t], 1);
    g_csr[slot] = s;
}

// ---------------------------------------------------------------------------
// One-time conversions.
__global__ void convert_x_kernel(const float* __restrict__ X) {
    int i = blockIdx.x * blockDim.x + threadIdx.x;
    size_t total8 = (size_t)N_NODES * D / 8;
    if ((size_t)i >= total8) return;
    const float4* src = (const float4*)X + (size_t)i * 2;
    float4 a = __ldg(src);
    float4 b = __ldg(src + 1);
    __half2 h0 = __floats2half2_rn(a.x, a.y);
    __half2 h1 = __floats2half2_rn(a.z, a.w);
    __half2 h2 = __floats2half2_rn(b.x, b.y);
    __half2 h3 = __floats2half2_rn(b.z, b.w);
    uint4 u;
    u.x = *(uint32_t*)&h0; u.y = *(uint32_t*)&h1;
    u.z = *(uint32_t*)&h2; u.w = *(uint32_t*)&h3;
    *((uint4*)g_Xh + i) = u;
}

// W[r][k][n] f32 -> g_Wt[r][n][k] f16 (transposed per relation).
__global__ void convert_w_kernel(const float* __restrict__ W) {
    int i = blockIdx.x * blockDim.x + threadIdx.x;
    if (i >= N_REL * D * D) return;
    int r = i >> 14;
    int rem = i & 16383;
    int k = rem >> 7;
    int n = rem & 127;
    g_Wt[((size_t)r * D + n) * D + k] = __float2half_rn(__ldg(&W[i]));
}

// ---------------------------------------------------------------------------
// FP16 tensor-core GEMM producing Y' = rs_out_r * (Xh @ W_r), stored fp16.
// C-block: 128x128; grid.y = relation. K = 128, BK = 32. 8 warps (2M x 4N),
// warp tile 64x32, m16n8k16 f16 mma, f32 acc. Smem stride 20 words.
#define GBM 128
#define GBN 128
#define GBK 32
#define SSTRIDE 20

__device__ __forceinline__ void mma_f16(float* d, const uint32_t* a,
                                        const uint32_t* b) {
    asm volatile(
        "mma.sync.aligned.m16n8k16.row.col.f32.f16.f16.f32 "
        "{%0,%1,%2,%3}, {%4,%5,%6,%7}, {%8,%9}, {%0,%1,%2,%3};"
        : "+f"(d[0]), "+f"(d[1]), "+f"(d[2]), "+f"(d[3])
        : "r"(a[0]), "r"(a[1]), "r"(a[2]), "r"(a[3]), "r"(b[0]), "r"(b[1]));
}

__global__ __launch_bounds__(256, 2)
void gemm_f16_kernel(const __half* __restrict__ Xh, const __half* __restrict__ Wt,
                     __half* __restrict__ Y) {
    __shared__ __align__(16) uint32_t As[GBM][SSTRIDE];
    __shared__ __align__(16) uint32_t Bs[GBN][SSTRIDE];

    int tid  = threadIdx.x;
    int wid  = tid >> 5;
    int lane = tid & 31;
    int lg   = lane >> 2;
    int lt   = lane & 3;
    int warp_m = wid & 1;
    int warp_n = wid >> 1;
    int row0 = blockIdx.x * GBM;
    int rel  = blockIdx.y;
    const __half* Bt = Wt + (size_t)rel * (D * D);

    float acc[4][4][4];
#pragma unroll
    for (int mi = 0; mi < 4; mi++)
#pragma unroll
        for (int ni = 0; ni < 4; ni++)
#pragma unroll
            for (int j = 0; j < 4; j++) acc[mi][ni][j] = 0.0f;

    for (int k0 = 0; k0 < D; k0 += GBK) {
#pragma unroll
        for (int i = 0; i < 2; i++) {
            int idx = tid + i * 256;
            int row = idx >> 2;
            int ch  = idx & 3;
            int grow = min(row0 + row, N_NODES - 1);
            uint4 u = __ldg((const uint4*)(Xh + (size_t)grow * D + k0 + ch * 8));
            *(uint4*)&As[row][ch * 4] = u;
        }
#pragma unroll
        for (int i = 0; i < 2; i++) {
            int idx = tid + i * 256;
            int col = idx >> 2;
            int ch  = idx & 3;
            uint4 u = __ldg((const uint4*)(Bt + (size_t)col * D + k0 + ch * 8));
            *(uint4*)&Bs[col][ch * 4] = u;
        }
        __syncthreads();

#pragma unroll
        for (int ks = 0; ks < 2; ks++) {
            int kc = ks * 8;
            uint32_t af[4][4];
            uint32_t bf[4][2];
#pragma unroll
            for (int mi = 0; mi < 4; mi++) {
                int base = warp_m * 64 + mi * 16;
                af[mi][0] = As[base + lg    ][kc + lt    ];
                af[mi][1] = As[base + lg + 8][kc + lt    ];
                af[mi][2] = As[base + lg    ][kc + lt + 4];
                af[mi][3] = As[base + lg + 8][kc + lt + 4];
            }
#pragma unroll
            for (int ni = 0; ni < 4; ni++) {
                int col = warp_n * 32 + ni * 8 + lg;
                bf[ni][0] = Bs[col][kc + lt    ];
                bf[ni][1] = Bs[col][kc + lt + 4];
            }
#pragma unroll
            for (int mi = 0; mi < 4; mi++)
#pragma unroll
                for (int ni = 0; ni < 4; ni++)
                    mma_f16(acc[mi][ni], af[mi], bf[ni]);
        }
        __syncthreads();
    }

    // Epilogue: scale by rsqrt(max(deg_out,1)) computed inline from counts.
    const int* cnt_out = g_cnt_out + (size_t)rel * N_NODES;
#pragma unroll
    for (int mi = 0; mi < 4; mi++) {
        int r = row0 + warp_m * 64 + mi * 16 + lg;
        float s0 = 0.0f, s1 = 0.0f;
        if (r < N_NODES)
            s0 = rsqrtf(fmaxf((float)__ldg(&cnt_out[r]), 1.0f));
        if (r + 8 < N_NODES)
            s1 = rsqrtf(fmaxf((float)__ldg(&cnt_out[r + 8]), 1.0f));
#pragma unroll
        for (int ni = 0; ni < 4; ni++) {
            int c = warp_n * 32 + ni * 8 + 2 * lt;
            if (r < N_NODES) {
                __half2 h = __floats2half2_rn(acc[mi][ni][0] * s0,
                                              acc[mi][ni][1] * s0);
                *(__half2*)(Y + (size_t)r * KTOT + rel * D + c) = h;
            }
            if (r + 8 < N_NODES) {
                __half2 h = __floats2half2_rn(acc[mi][ni][2] * s1,
                                              acc[mi][ni][3] * s1);
                *(__half2*)(Y + (size_t)(r + 8) * KTOT + rel * D + c) = h;
            }
        }
    }
}

// ---------------------------------------------------------------------------
// Gather: one warp per dst node. Lane l owns cols 4l..4l+3. For each relation,
// sum Y[src] rows over the CSR in-edge list (2-edge unroll for MLP), scale by
// rsqrt(deg_in) factored OUT of the sum, accumulate across relations, write
// the out row exactly once. No atomics anywhere.
__global__ __launch_bounds__(256)
void gather_kernel(const __half* __restrict__ Y, float* __restrict__ out) {
    int warp = (blockIdx.x * blockDim.x + threadIdx.x) >> 5;
    if (warp >= N_NODES) return;
    int lane = threadIdx.x & 31;
    int t = warp;

    float a0 = 0.f, a1 = 0.f, a2 = 0.f, a3 = 0.f;

#pragma unroll
    for (int r = 0; r < N_REL; r++) {
        int start = __ldg(&g_rowptr[r * N_NODES + t]);
        int end   = __ldg(&g_rowptr[r * N_NODES + t + 1]);
        float ci = rsqrtf(fmaxf((float)(end - start), 1.0f));
        const __half* Yr = Y + (size_t)r * D;

        float r0 = 0.f, r1 = 0.f, r2 = 0.f, r3 = 0.f;
        int j = start;
        for (; j + 2 <= end; j += 2) {
            int s0 = __ldg(&g_csr[j]);
            int s1 = __ldg(&g_csr[j + 1]);
            uint2 v0 = __ldg((const uint2*)(Yr + (size_t)s0 * KTOT) + lane);
            uint2 v1 = __ldg((const uint2*)(Yr + (size_t)s1 * KTOT) + lane);
            float2 p0 = __half22float2(*(__half2*)&v0.x);
            float2 p1 = __half22float2(*(__half2*)&v0.y);
            float2 q0 = __half22float2(*(__half2*)&v1.x);
            float2 q1 = __half22float2(*(__half2*)&v1.y);
            r0 += p0.x + q0.x;
            r1 += p0.y + q0.y;
            r2 += p1.x + q1.x;
            r3 += p1.y + q1.y;
        }
        if (j < end) {
            int s0 = __ldg(&g_csr[j]);
            uint2 v0 = __ldg((const uint2*)(Yr + (size_t)s0 * KTOT) + lane);
            float2 p0 = __half22float2(*(__half2*)&v0.x);
            float2 p1 = __half22float2(*(__half2*)&v0.y);
            r0 += p0.x; r1 += p0.y; r2 += p1.x; r3 += p1.y;
        }
        a0 = fmaf(ci, r0, a0);
        a1 = fmaf(ci, r1, a1);
        a2 = fmaf(ci, r2, a2);
        a3 = fmaf(ci, r3, a3);
    }

    float4 o = make_float4(a0, a1, a2, a3);
    *(float4*)(out + (size_t)t * D + lane * 4) = o;
}

// ---------------------------------------------------------------------------
extern "C" void kernel_launch(void* const* d_in, const int* in_sizes, int n_in,
                              void* d_out, int out_size) {
    const int*   edges = (const int*)d_in[0];    // [4, 2, 600000] int32
    const float* X     = (const float*)d_in[1];  // [100000, 128] f32
    const float* W     = (const float*)d_in[2];  // [4, 128, 128] f32
    float*       out   = (float*)d_out;          // [100000, 128] f32

    void *yp, *xhp, *wtp, *cop, *cip;
    cudaGetSymbolAddress(&yp,  g_Y);
    cudaGetSymbolAddress(&xhp, g_Xh);
    cudaGetSymbolAddress(&wtp, g_Wt);
    cudaGetSymbolAddress(&cop, g_cnt_out);
    cudaGetSymbolAddress(&cip, g_cnt_in);

    cudaMemsetAsync(cop, 0, sizeof(int) * RN, 0);
    cudaMemsetAsync(cip, 0, sizeof(int) * RN, 0);

    {
        int total = N_REL * N_EDGES;
        degree_kernel<<<(total + 255) / 256, 256>>>(edges);
    }
    {
        size_t total8 = (size_t)N_NODES * D / 8;
        convert_x_kernel<<<(int)((total8 + 255) / 256), 256>>>(X);
    }
    {
        int total = N_REL * D * D;
        convert_w_kernel<<<(total + 255) / 256, 256>>>(W);
    }
    scan_phase1_kernel<<<SCAN_NBLK, SCAN_BLK>>>();
    scan_phase2_kernel<<<1, 512>>>();
    scan_phase3_kernel<<<SCAN_NBLK, SCAN_BLK>>>();
    {
        int total = N_REL * N_EDGES;
        csr_fill_kernel<<<(total + 255) / 256, 256>>>(edges);
    }
    {
        dim3 grid((N_NODES + GBM - 1) / GBM, N_REL);   // (782, 4)
        gemm_f16_kernel<<<grid, 256>>>((const __half*)xhp, (const __half*)wtp,
                                       (__half*)yp);
    }
    {
        // one warp per dst node
        long long threads = (long long)N_NODES * 32;
        int blocks = (int)((threads + 255) / 256);
        gather_kernel<<<blocks, 256>>>((const __half*)yp, out);
    }
}

// round 11
// speedup vs baseline: 2.4872x; 1.1101x over previous
#include <cuda_runtime.h>
#include <cuda_fp16.h>
#include <cstdint>

#define N_NODES 100000
#define N_REL   4
#define N_EDGES 600000
#define D       128
#define KTOT    (N_REL * D)   // 512
#define RN      (N_REL * N_NODES)   // 400000
#define TOT_EDGES (N_REL * N_EDGES) // 2400000
#define SCAN_BLK 1024
#define SCAN_NBLK ((N_NODES + SCAN_BLK - 1) / SCAN_BLK)   // 98

// Scratch (device globals — no allocation allowed in kernel_launch)
__device__ __half g_Y [(size_t)N_NODES * KTOT];      // [N, 4, 128] fp16: rs_out*(X@W_r)
__device__ __half g_Xh[(size_t)N_NODES * D];         // X in fp16
__device__ __half g_Wt[(size_t)N_REL * D * D];       // W[r] transposed: [r][n][k] fp16
__device__ int    g_cnt_out[RN];                     // out-degree  [r][n]
__device__ int    g_cnt_in [RN];                     // in-degree   [r][n]
__device__ int    g_rowptr [N_NODES + 1];            // CSR row ptr over dst nodes
__device__ int    g_cursor [N_NODES];                // fill cursors
__device__ int    g_blocksum[SCAN_NBLK];             // per-block totals (phase 1)
__device__ int    g_blockoff[SCAN_NBLK];             // exclusive block offsets (phase 2)
__device__ int    g_csr    [TOT_EDGES];              // packed (4*src + rel) by dst

// ---------------------------------------------------------------------------
// Degree histogram: one thread per (relation, edge), two int atomics.
__global__ void degree_kernel(const int* __restrict__ edges) {
    int i = blockIdx.x * blockDim.x + threadIdx.x;
    if (i >= TOT_EDGES) return;
    int r = i / N_EDGES;
    int e = i - r * N_EDGES;
    int s = edges[(r * 2 + 0) * N_EDGES + e];
    int t = edges[(r * 2 + 1) * N_EDGES + e];
    atomicAdd(&g_cnt_out[r * N_NODES + s], 1);
    atomicAdd(&g_cnt_in [r * N_NODES + t], 1);
}

// ---------------------------------------------------------------------------
// 3-phase parallel exclusive scan over combined in-degree per dst node
// (sum over the 4 relations) -> g_rowptr (+ g_cursor copy).
__global__ __launch_bounds__(SCAN_BLK) void scan_phase1_kernel() {
    __shared__ int s[SCAN_BLK];
    int tid = threadIdx.x;
    int i = blockIdx.x * SCAN_BLK + tid;
    int v = 0;
    if (i < N_NODES) {
        v = __ldg(&g_cnt_in[0 * N_NODES + i]) + __ldg(&g_cnt_in[1 * N_NODES + i])
          + __ldg(&g_cnt_in[2 * N_NODES + i]) + __ldg(&g_cnt_in[3 * N_NODES + i]);
    }
    s[tid] = v;
    __syncthreads();
#pragma unroll
    for (int off = 1; off < SCAN_BLK; off <<= 1) {
        int add = (tid >= off) ? s[tid - off] : 0;
        __syncthreads();
        s[tid] += add;
        __syncthreads();
    }
    if (i < N_NODES) g_rowptr[i] = s[tid] - v;      // exclusive within block
    if (tid == SCAN_BLK - 1) g_blocksum[blockIdx.x] = s[tid];
}

// Phase 2: single small block scans the 98 block sums (exclusive).
__global__ __launch_bounds__(128) void scan_phase2_kernel() {
    __shared__ int s[128];
    int tid = threadIdx.x;
    int v = (tid < SCAN_NBLK) ? g_blocksum[tid] : 0;
    s[tid] = v;
    __syncthreads();
#pragma unroll
    for (int off = 1; off < 128; off <<= 1) {
        int add = (tid >= off) ? s[tid - off] : 0;
        __syncthreads();
        s[tid] += add;
        __syncthreads();
    }
    if (tid < SCAN_NBLK) g_blockoff[tid] = s[tid] - v;
    if (tid == 0) g_rowptr[N_NODES] = TOT_EDGES;    // grand total is constant
}

// Phase 3: add block offsets; write cursor copy in the same pass.
__global__ __launch_bounds__(SCAN_BLK) void scan_phase3_kernel() {
    int i = blockIdx.x * SCAN_BLK + threadIdx.x;
    if (i >= N_NODES) return;
    int v = g_rowptr[i] + __ldg(&g_blockoff[blockIdx.x]);
    g_rowptr[i] = v;
    g_cursor[i] = v;
}

// ---------------------------------------------------------------------------
// CSR fill: per edge, grab a slot in its dst bucket, store packed (4*src+rel).
__global__ void csr_fill_kernel(const int* __restrict__ edges) {
    int i = blockIdx.x * blockDim.x + threadIdx.x;
    if (i >= TOT_EDGES) return;
    int r = i / N_EDGES;
    int e = i - r * N_EDGES;
    int s = edges[(r * 2 + 0) * N_EDGES + e];
    int t = edges[(r * 2 + 1) * N_EDGES + e];
    int slot = atomicAdd(&g_cursor[t], 1);
    g_csr[slot] = (s << 2) | r;     // packed row index into Y: (4*src+rel)
}

// ---------------------------------------------------------------------------
// One-time conversions.
__global__ void convert_x_kernel(const float* __restrict__ X) {
    int i = blockIdx.x * blockDim.x + threadIdx.x;
    size_t total8 = (size_t)N_NODES * D / 8;
    if ((size_t)i >= total8) return;
    const float4* src = (const float4*)X + (size_t)i * 2;
    float4 a = __ldg(src);
    float4 b = __ldg(src + 1);
    __half2 h0 = __floats2half2_rn(a.x, a.y);
    __half2 h1 = __floats2half2_rn(a.z, a.w);
    __half2 h2 = __floats2half2_rn(b.x, b.y);
    __half2 h3 = __floats2half2_rn(b.z, b.w);
    uint4 u;
    u.x = *(uint32_t*)&h0; u.y = *(uint32_t*)&h1;
    u.z = *(uint32_t*)&h2; u.w = *(uint32_t*)&h3;
    *((uint4*)g_Xh + i) = u;
}

// W[r][k][n] f32 -> g_Wt[r][n][k] f16 (transposed per relation).
__global__ void convert_w_kernel(const float* __restrict__ W) {
    int i = blockIdx.x * blockDim.x + threadIdx.x;
    if (i >= N_REL * D * D) return;
    int r = i >> 14;
    int rem = i & 16383;
    int k = rem >> 7;
    int n = rem & 127;
    g_Wt[((size_t)r * D + n) * D + k] = __float2half_rn(__ldg(&W[i]));
}

// ---------------------------------------------------------------------------
// FP16 tensor-core GEMM producing Y' = rs_out_r * (Xh @ W_r), stored fp16.
// C-block: 128x128; grid.y = relation. K = 128, BK = 64 (2 k-iterations).
// 8 warps (2M x 4N), warp tile 64x32, m16n8k16 f16 mma, f32 acc.
// Smem: half2 words, 32 words per BK=64 row, stride 36 -> conflict-free frags.
#define GBM 128
#define GBN 128
#define GBK 64
#define SSTRIDE 36

__device__ __forceinline__ void mma_f16(float* d, const uint32_t* a,
                                        const uint32_t* b) {
    asm volatile(
        "mma.sync.aligned.m16n8k16.row.col.f32.f16.f16.f32 "
        "{%0,%1,%2,%3}, {%4,%5,%6,%7}, {%8,%9}, {%0,%1,%2,%3};"
        : "+f"(d[0]), "+f"(d[1]), "+f"(d[2]), "+f"(d[3])
        : "r"(a[0]), "r"(a[1]), "r"(a[2]), "r"(a[3]), "r"(b[0]), "r"(b[1]));
}

__global__ __launch_bounds__(256, 2)
void gemm_f16_kernel(const __half* __restrict__ Xh, const __half* __restrict__ Wt,
                     __half* __restrict__ Y) {
    __shared__ __align__(16) uint32_t As[GBM][SSTRIDE];
    __shared__ __align__(16) uint32_t Bs[GBN][SSTRIDE];

    int tid  = threadIdx.x;
    int wid  = tid >> 5;
    int lane = tid & 31;
    int lg   = lane >> 2;
    int lt   = lane & 3;
    int warp_m = wid & 1;
    int warp_n = wid >> 1;
    int row0 = blockIdx.x * GBM;
    int rel  = blockIdx.y;
    const __half* Bt = Wt + (size_t)rel * (D * D);

    float acc[4][4][4];
#pragma unroll
    for (int mi = 0; mi < 4; mi++)
#pragma unroll
        for (int ni = 0; ni < 4; ni++)
#pragma unroll
            for (int j = 0; j < 4; j++) acc[mi][ni][j] = 0.0f;

    for (int k0 = 0; k0 < D; k0 += GBK) {
        // Stage A: 128 rows x 64 halves = 1024 uint4 chunks, 4 per thread.
#pragma unroll
        for (int i = 0; i < 4; i++) {
            int idx = tid + i * 256;
            int row = idx >> 3;           // 0..127
            int ch  = idx & 7;            // 16B chunk within row (8 chunks)
            int grow = min(row0 + row, N_NODES - 1);
            uint4 u = __ldg((const uint4*)(Xh + (size_t)grow * D + k0 + ch * 8));
            *(uint4*)&As[row][ch * 4] = u;
        }
        // Stage B: 128 cols x 64 halves from Wt rows.
#pragma unroll
        for (int i = 0; i < 4; i++) {
            int idx = tid + i * 256;
            int col = idx >> 3;
            int ch  = idx & 7;
            uint4 u = __ldg((const uint4*)(Bt + (size_t)col * D + k0 + ch * 8));
            *(uint4*)&Bs[col][ch * 4] = u;
        }
        __syncthreads();

#pragma unroll
        for (int ks = 0; ks < 4; ks++) {      // four k16 steps per BK=64
            int kc = ks * 8;
            uint32_t af[4][4];
            uint32_t bf[4][2];
#pragma unroll
            for (int mi = 0; mi < 4; mi++) {
                int base = warp_m * 64 + mi * 16;
                af[mi][0] = As[base + lg    ][kc + lt    ];
                af[mi][1] = As[base + lg + 8][kc + lt    ];
                af[mi][2] = As[base + lg    ][kc + lt + 4];
                af[mi][3] = As[base + lg + 8][kc + lt + 4];
            }
#pragma unroll
            for (int ni = 0; ni < 4; ni++) {
                int col = warp_n * 32 + ni * 8 + lg;
                bf[ni][0] = Bs[col][kc + lt    ];
                bf[ni][1] = Bs[col][kc + lt + 4];
            }
#pragma unroll
            for (int mi = 0; mi < 4; mi++)
#pragma unroll
                for (int ni = 0; ni < 4; ni++)
                    mma_f16(acc[mi][ni], af[mi], bf[ni]);
        }
        __syncthreads();
    }

    // Epilogue: scale by rsqrt(max(deg_out,1)) computed inline from counts.
    const int* cnt_out = g_cnt_out + (size_t)rel * N_NODES;
#pragma unroll
    for (int mi = 0; mi < 4; mi++) {
        int r = row0 + warp_m * 64 + mi * 16 + lg;
        float s0 = 0.0f, s1 = 0.0f;
        if (r < N_NODES)
            s0 = rsqrtf(fmaxf((float)__ldg(&cnt_out[r]), 1.0f));
        if (r + 8 < N_NODES)
            s1 = rsqrtf(fmaxf((float)__ldg(&cnt_out[r + 8]), 1.0f));
#pragma unroll
        for (int ni = 0; ni < 4; ni++) {
            int c = warp_n * 32 + ni * 8 + 2 * lt;
            if (r < N_NODES) {
                __half2 h = __floats2half2_rn(acc[mi][ni][0] * s0,
                                              acc[mi][ni][1] * s0);
                *(__half2*)(Y + (size_t)r * KTOT + rel * D + c) = h;
            }
            if (r + 8 < N_NODES) {
                __half2 h = __floats2half2_rn(acc[mi][ni][2] * s1,
                                              acc[mi][ni][3] * s1);
                *(__half2*)(Y + (size_t)(r + 8) * KTOT + rel * D + c) = h;
            }
        }
    }
}

// ---------------------------------------------------------------------------
// Gather: one warp per dst node, ONE loop over all in-edges of all relations
// (avg 24 edges), 4-edge unrolled for deep MLP. Lane l owns cols 4l..4l+3.
// Packed csr value p = 4*src+rel is directly the Y row index; per-edge coef
// rsqrt(deg_in[rel][t]) selected from 4 preloaded registers via p&3.
__global__ __launch_bounds__(256)
void gather_kernel(const __half* __restrict__ Y, float* __restrict__ out) {
    int warp = (blockIdx.x * blockDim.x + threadIdx.x) >> 5;
    if (warp >= N_NODES) return;
    int lane = threadIdx.x & 31;
    int t = warp;

    int start = __ldg(&g_rowptr[t]);
    int end   = __ldg(&g_rowptr[t + 1]);
    float cs0 = rsqrtf(fmaxf((float)__ldg(&g_cnt_in[0 * N_NODES + t]), 1.0f));
    float cs1 = rsqrtf(fmaxf((float)__ldg(&g_cnt_in[1 * N_NODES + t]), 1.0f));
    float cs2 = rsqrtf(fmaxf((float)__ldg(&g_cnt_in[2 * N_NODES + t]), 1.0f));
    float cs3 = rsqrtf(fmaxf((float)__ldg(&g_cnt_in[3 * N_NODES + t]), 1.0f));

    float a0 = 0.f, a1 = 0.f, a2 = 0.f, a3 = 0.f;

    int j = start;
    for (; j + 4 <= end; j += 4) {
        int p0 = __ldg(&g_csr[j]);
        int p1 = __ldg(&g_csr[j + 1]);
        int p2 = __ldg(&g_csr[j + 2]);
        int p3 = __ldg(&g_csr[j + 3]);
        uint2 v0 = __ldg((const uint2*)(Y + (size_t)p0 * D) + lane);
        uint2 v1 = __ldg((const uint2*)(Y + (size_t)p1 * D) + lane);
        uint2 v2 = __ldg((const uint2*)(Y + (size_t)p2 * D) + lane);
        uint2 v3 = __ldg((const uint2*)(Y + (size_t)p3 * D) + lane);
        int r0 = p0 & 3, r1 = p1 & 3, r2 = p2 & 3, r3 = p3 & 3;
        float c0 = (r0 == 0) ? cs0 : (r0 == 1) ? cs1 : (r0 == 2) ? cs2 : cs3;
        float c1 = (r1 == 0) ? cs0 : (r1 == 1) ? cs1 : (r1 == 2) ? cs2 : cs3;
        float c2 = (r2 == 0) ? cs0 : (r2 == 1) ? cs1 : (r2 == 2) ? cs2 : cs3;
        float c3 = (r3 == 0) ? cs0 : (r3 == 1) ? cs1 : (r3 == 2) ? cs2 : cs3;
        {
            float2 x0 = __half22float2(*(__half2*)&v0.x);
            float2 x1 = __half22float2(*(__half2*)&v0.y);
            a0 = fmaf(c0, x0.x, a0); a1 = fmaf(c0, x0.y, a1);
            a2 = fmaf(c0, x1.x, a2); a3 = fmaf(c0, x1.y, a3);
        }
        {
            float2 x0 = __half22float2(*(__half2*)&v1.x);
            float2 x1 = __half22float2(*(__half2*)&v1.y);
            a0 = fmaf(c1, x0.x, a0); a1 = fmaf(c1, x0.y, a1);
            a2 = fmaf(c1, x1.x, a2); a3 = fmaf(c1, x1.y, a3);
        }
        {
            float2 x0 = __half22float2(*(__half2*)&v2.x);
            float2 x1 = __half22float2(*(__half2*)&v2.y);
            a0 = fmaf(c2, x0.x, a0); a1 = fmaf(c2, x0.y, a1);
            a2 = fmaf(c2, x1.x, a2); a3 = fmaf(c2, x1.y, a3);
        }
        {
            float2 x0 = __half22float2(*(__half2*)&v3.x);
            float2 x1 = __half22float2(*(__half2*)&v3.y);
            a0 = fmaf(c3, x0.x, a0); a1 = fmaf(c3, x0.y, a1);
            a2 = fmaf(c3, x1.x, a2); a3 = fmaf(c3, x1.y, a3);
        }
    }
    for (; j < end; j++) {
        int p0 = __ldg(&g_csr[j]);
        uint2 v0 = __ldg((const uint2*)(Y + (size_t)p0 * D) + lane);
        int r0 = p0 & 3;
        float c0 = (r0 == 0) ? cs0 : (r0 == 1) ? cs1 : (r0 == 2) ? cs2 : cs3;
        float2 x0 = __half22float2(*(__half2*)&v0.x);
        float2 x1 = __half22float2(*(__half2*)&v0.y);
        a0 = fmaf(c0, x0.x, a0); a1 = fmaf(c0, x0.y, a1);
        a2 = fmaf(c0, x1.x, a2); a3 = fmaf(c0, x1.y, a3);
    }

    float4 o = make_float4(a0, a1, a2, a3);
    *(float4*)(out + (size_t)t * D + lane * 4) = o;
}

// ---------------------------------------------------------------------------
extern "C" void kernel_launch(void* const* d_in, const int* in_sizes, int n_in,
                              void* d_out, int out_size) {
    const int*   edges = (const int*)d_in[0];    // [4, 2, 600000] int32
    const float* X     = (const float*)d_in[1];  // [100000, 128] f32
    const float* W     = (const float*)d_in[2];  // [4, 128, 128] f32
    float*       out   = (float*)d_out;          // [100000, 128] f32

    void *yp, *xhp, *wtp, *cop, *cip;
    cudaGetSymbolAddress(&yp,  g_Y);
    cudaGetSymbolAddress(&xhp, g_Xh);
    cudaGetSymbolAddress(&wtp, g_Wt);
    cudaGetSymbolAddress(&cop, g_cnt_out);
    cudaGetSymbolAddress(&cip, g_cnt_in);

    cudaMemsetAsync(cop, 0, sizeof(int) * RN, 0);
    cudaMemsetAsync(cip, 0, sizeof(int) * RN, 0);

    {
        degree_kernel<<<(TOT_EDGES + 255) / 256, 256>>>(edges);
    }
    {
        size_t total8 = (size_t)N_NODES * D / 8;
        convert_x_kernel<<<(int)((total8 + 255) / 256), 256>>>(X);
    }
    {
        int total = N_REL * D * D;
        convert_w_kernel<<<(total + 255) / 256, 256>>>(W);
    }
    scan_phase1_kernel<<<SCAN_NBLK, SCAN_BLK>>>();
    scan_phase2_kernel<<<1, 128>>>();
    scan_phase3_kernel<<<SCAN_NBLK, SCAN_BLK>>>();
    {
        csr_fill_kernel<<<(TOT_EDGES + 255) / 256, 256>>>(edges);
    }
    {
        dim3 grid((N_NODES + GBM - 1) / GBM, N_REL);   // (782, 4)
        gemm_f16_kernel<<<grid, 256>>>((const __half*)xhp, (const __half*)wtp,
                                       (__half*)yp);
    }
    {
        // one warp per dst node
        long long threads = (long long)N_NODES * 32;
        int blocks = (int)((threads + 255) / 256);
        gather_kernel<<<blocks, 256>>>((const __half*)yp, out);
    }
}